// round 9
// baseline (speedup 1.0000x reference)
#include <cuda_runtime.h>

// Gated DeltaNet single step, fully folded:
//   qk  = q . k
//   w   = q - qk*beta*k            (per-head, 128 floats)
//   out = g * (w . S[:,v]) + qk*beta*v[v]
// ONE matvec against state (was two). One warp per (b,h), 8 warps/CTA,
// float4 lanes. HBM-bound: 805MB single pass; plateau at ~6.5 TB/s.

#define DK 128
#define DV 128
#define WARPS_PER_CTA 8

__global__ __launch_bounds__(WARPS_PER_CTA * 32)
void deltanet_step_kernel(const float* __restrict__ q,
                          const float* __restrict__ k,
                          const float* __restrict__ v,
                          const float* __restrict__ beta,
                          const float* __restrict__ gate,
                          const float* __restrict__ state,
                          float* __restrict__ out,
                          int BH) {
    const int warp = threadIdx.x >> 5;
    const int lane = threadIdx.x & 31;
    const int bh   = blockIdx.x * WARPS_PER_CTA + warp;
    if (bh >= BH) return;

    __shared__ float sw[WARPS_PER_CTA][DK];

    const float4 q4 = reinterpret_cast<const float4*>(q + (size_t)bh * DK)[lane];
    const float4 k4 = reinterpret_cast<const float4*>(k + (size_t)bh * DK)[lane];

    // qk = q . k via butterfly
    float qk = q4.x * k4.x + q4.y * k4.y + q4.z * k4.z + q4.w * k4.w;
    #pragma unroll
    for (int off = 16; off > 0; off >>= 1)
        qk += __shfl_xor_sync(0xFFFFFFFFu, qk, off);

    const float bt  = beta[bh];
    const float g   = gate[bh];
    const float qkb = qk * bt;

    // w = q - qk*beta*k  -> smem for broadcast in the matvec
    float4 w4;
    w4.x = fmaf(-qkb, k4.x, q4.x);
    w4.y = fmaf(-qkb, k4.y, q4.y);
    w4.z = fmaf(-qkb, k4.z, q4.z);
    w4.w = fmaf(-qkb, k4.w, q4.w);
    reinterpret_cast<float4*>(sw[warp])[lane] = w4;
    __syncwarp();

    const float4* S = reinterpret_cast<const float4*>(state + (size_t)bh * (DK * DV));

    float4 acc = make_float4(0.f, 0.f, 0.f, 0.f);

    #pragma unroll 8
    for (int kk = 0; kk < DK; ++kk) {
        const float4 s = S[kk * (DV / 4) + lane];   // warp reads full 512B row
        const float wc = sw[warp][kk];              // smem broadcast
        acc.x = fmaf(wc, s.x, acc.x);
        acc.y = fmaf(wc, s.y, acc.y);
        acc.z = fmaf(wc, s.z, acc.z);
        acc.w = fmaf(wc, s.w, acc.w);
    }

    const float4 vv = reinterpret_cast<const float4*>(v + (size_t)bh * DV)[lane];

    float4 o;
    o.x = fmaf(g, acc.x, qkb * vv.x);
    o.y = fmaf(g, acc.y, qkb * vv.y);
    o.z = fmaf(g, acc.z, qkb * vv.z);
    o.w = fmaf(g, acc.w, qkb * vv.w);
    reinterpret_cast<float4*>(out + (size_t)bh * DV)[lane] = o;
}

extern "C" void kernel_launch(void* const* d_in, const int* in_sizes, int n_in,
                              void* d_out, int out_size) {
    const float* q     = (const float*)d_in[0];
    const float* k     = (const float*)d_in[1];
    const float* v     = (const float*)d_in[2];
    const float* beta  = (const float*)d_in[3];
    const float* gate  = (const float*)d_in[4];
    const float* state = (const float*)d_in[5];
    float* out = (float*)d_out;

    const int BH = in_sizes[3];   // beta: B*H elements
    const int grid = (BH + WARPS_PER_CTA - 1) / WARPS_PER_CTA;

    deltanet_step_kernel<<<grid, WARPS_PER_CTA * 32>>>(q, k, v, beta, gate, state, out, BH);
}

// round 10
// speedup vs baseline: 1.0560x; 1.0560x over previous
#include <cuda_runtime.h>

// Gated DeltaNet single step, folded to ONE matvec:
//   qk  = q . k
//   w   = q - qk*beta*k
//   out = g * (w . S[:,v]) + qk*beta*v[v]
// One warp per (b,h), 8 warps/CTA, float4 lanes.
// Manual batch-8 load preload keeps 8 float4 LDGs in flight per thread;
// __launch_bounds__(256,4) grants a 64-reg budget so ptxas can't collapse it.

#define DK 128
#define DV 128
#define WARPS_PER_CTA 8
#define BATCH 8

__global__ __launch_bounds__(WARPS_PER_CTA * 32, 4)
void deltanet_step_kernel(const float* __restrict__ q,
                          const float* __restrict__ k,
                          const float* __restrict__ v,
                          const float* __restrict__ beta,
                          const float* __restrict__ gate,
                          const float* __restrict__ state,
                          float* __restrict__ out,
                          int BH) {
    const int warp = threadIdx.x >> 5;
    const int lane = threadIdx.x & 31;
    const int bh   = blockIdx.x * WARPS_PER_CTA + warp;
    if (bh >= BH) return;

    __shared__ float sw[WARPS_PER_CTA][DK];

    const float4 q4 = reinterpret_cast<const float4*>(q + (size_t)bh * DK)[lane];
    const float4 k4 = reinterpret_cast<const float4*>(k + (size_t)bh * DK)[lane];

    // qk = q . k via butterfly
    float qk = q4.x * k4.x + q4.y * k4.y + q4.z * k4.z + q4.w * k4.w;
    #pragma unroll
    for (int off = 16; off > 0; off >>= 1)
        qk += __shfl_xor_sync(0xFFFFFFFFu, qk, off);

    const float bt  = beta[bh];
    const float g   = gate[bh];
    const float qkb = qk * bt;

    // w = q - qk*beta*k  -> smem for broadcast in the matvec
    float4 w4;
    w4.x = fmaf(-qkb, k4.x, q4.x);
    w4.y = fmaf(-qkb, k4.y, q4.y);
    w4.z = fmaf(-qkb, k4.z, q4.z);
    w4.w = fmaf(-qkb, k4.w, q4.w);
    reinterpret_cast<float4*>(sw[warp])[lane] = w4;
    __syncwarp();

    const float4* S = reinterpret_cast<const float4*>(state + (size_t)bh * (DK * DV));

    float4 acc = make_float4(0.f, 0.f, 0.f, 0.f);

    for (int b = 0; b < DK; b += BATCH) {
        // Front-batched loads: 8 independent float4 LDGs in flight.
        float4 sbuf[BATCH];
        #pragma unroll
        for (int i = 0; i < BATCH; ++i)
            sbuf[i] = S[(b + i) * (DV / 4) + lane];

        #pragma unroll
        for (int i = 0; i < BATCH; ++i) {
            const float wc = sw[warp][b + i];
            acc.x = fmaf(wc, sbuf[i].x, acc.x);
            acc.y = fmaf(wc, sbuf[i].y, acc.y);
            acc.z = fmaf(wc, sbuf[i].z, acc.z);
            acc.w = fmaf(wc, sbuf[i].w, acc.w);
        }
    }

    const float4 vv = reinterpret_cast<const float4*>(v + (size_t)bh * DV)[lane];

    float4 o;
    o.x = fmaf(g, acc.x, qkb * vv.x);
    o.y = fmaf(g, acc.y, qkb * vv.y);
    o.z = fmaf(g, acc.z, qkb * vv.z);
    o.w = fmaf(g, acc.w, qkb * vv.w);
    reinterpret_cast<float4*>(out + (size_t)bh * DV)[lane] = o;
}

extern "C" void kernel_launch(void* const* d_in, const int* in_sizes, int n_in,
                              void* d_out, int out_size) {
    const float* q     = (const float*)d_in[0];
    const float* k     = (const float*)d_in[1];
    const float* v     = (const float*)d_in[2];
    const float* beta  = (const float*)d_in[3];
    const float* gate  = (const float*)d_in[4];
    const float* state = (const float*)d_in[5];
    float* out = (float*)d_out;

    const int BH = in_sizes[3];   // beta: B*H elements
    const int grid = (BH + WARPS_PER_CTA - 1) / WARPS_PER_CTA;

    deltanet_step_kernel<<<grid, WARPS_PER_CTA * 32>>>(q, k, v, beta, gate, state, out, BH);
}

// round 11
// speedup vs baseline: 1.0850x; 1.0275x over previous
#include <cuda_runtime.h>

// Gated DeltaNet single step, folded to ONE matvec:
//   qk  = q . k ;  w = q - qk*beta*k ;  out = g*(w . S[:,v]) + qk*beta*v
// One warp per (b,h), 8 warps/CTA, float4 lanes.
// Software-pipelined double buffer: 8 loads for batch b+1 issue while
// batch b's FMAs run -> 8-16 LDG.128 continuously in flight per thread.
// __launch_bounds__(256,2): 128-reg budget, no collapse, no spill.

#define DK 128
#define DV 128
#define WARPS_PER_CTA 8
#define BATCH 8
#define NBATCH (DK / BATCH)   // 16

__global__ __launch_bounds__(WARPS_PER_CTA * 32, 2)
void deltanet_step_kernel(const float* __restrict__ q,
                          const float* __restrict__ k,
                          const float* __restrict__ v,
                          const float* __restrict__ beta,
                          const float* __restrict__ gate,
                          const float* __restrict__ state,
                          float* __restrict__ out,
                          int BH) {
    const int warp = threadIdx.x >> 5;
    const int lane = threadIdx.x & 31;
    const int bh   = blockIdx.x * WARPS_PER_CTA + warp;
    if (bh >= BH) return;

    __shared__ float sw[WARPS_PER_CTA][DK];

    const float4 q4 = reinterpret_cast<const float4*>(q + (size_t)bh * DK)[lane];
    const float4 k4 = reinterpret_cast<const float4*>(k + (size_t)bh * DK)[lane];

    // qk = q . k via butterfly
    float qk = q4.x * k4.x + q4.y * k4.y + q4.z * k4.z + q4.w * k4.w;
    #pragma unroll
    for (int off = 16; off > 0; off >>= 1)
        qk += __shfl_xor_sync(0xFFFFFFFFu, qk, off);

    const float bt  = beta[bh];
    const float g   = gate[bh];
    const float qkb = qk * bt;

    // w = q - qk*beta*k  -> smem for broadcast in the matvec
    float4 w4;
    w4.x = fmaf(-qkb, k4.x, q4.x);
    w4.y = fmaf(-qkb, k4.y, q4.y);
    w4.z = fmaf(-qkb, k4.z, q4.z);
    w4.w = fmaf(-qkb, k4.w, q4.w);
    reinterpret_cast<float4*>(sw[warp])[lane] = w4;
    __syncwarp();

    const float4* S = reinterpret_cast<const float4*>(state + (size_t)bh * (DK * DV));

    float4 acc = make_float4(0.f, 0.f, 0.f, 0.f);

    float4 bufA[BATCH];
    float4 bufB[BATCH];

    // Prologue: fill buffer A with batch 0.
    #pragma unroll
    for (int i = 0; i < BATCH; ++i)
        bufA[i] = S[i * (DV / 4) + lane];

    #pragma unroll
    for (int b = 0; b < NBATCH; ++b) {
        float4* cur = (b & 1) ? bufB : bufA;
        float4* nxt = (b & 1) ? bufA : bufB;

        // Issue next batch's loads before consuming current batch.
        if (b + 1 < NBATCH) {
            const int base = (b + 1) * BATCH;
            #pragma unroll
            for (int i = 0; i < BATCH; ++i)
                nxt[i] = S[(base + i) * (DV / 4) + lane];
        }

        const int base = b * BATCH;
        #pragma unroll
        for (int i = 0; i < BATCH; ++i) {
            const float wc = sw[warp][base + i];
            acc.x = fmaf(wc, cur[i].x, acc.x);
            acc.y = fmaf(wc, cur[i].y, acc.y);
            acc.z = fmaf(wc, cur[i].z, acc.z);
            acc.w = fmaf(wc, cur[i].w, acc.w);
        }
    }

    const float4 vv = reinterpret_cast<const float4*>(v + (size_t)bh * DV)[lane];

    float4 o;
    o.x = fmaf(g, acc.x, qkb * vv.x);
    o.y = fmaf(g, acc.y, qkb * vv.y);
    o.z = fmaf(g, acc.z, qkb * vv.z);
    o.w = fmaf(g, acc.w, qkb * vv.w);
    reinterpret_cast<float4*>(out + (size_t)bh * DV)[lane] = o;
}

extern "C" void kernel_launch(void* const* d_in, const int* in_sizes, int n_in,
                              void* d_out, int out_size) {
    const float* q     = (const float*)d_in[0];
    const float* k     = (const float*)d_in[1];
    const float* v     = (const float*)d_in[2];
    const float* beta  = (const float*)d_in[3];
    const float* gate  = (const float*)d_in[4];
    const float* state = (const float*)d_in[5];
    float* out = (float*)d_out;

    const int BH = in_sizes[3];   // beta: B*H elements
    const int grid = (BH + WARPS_PER_CTA - 1) / WARPS_PER_CTA;

    deltanet_step_kernel<<<grid, WARPS_PER_CTA * 32>>>(q, k, v, beta, gate, state, out, BH);
}

// round 12
// speedup vs baseline: 1.0931x; 1.0074x over previous
#include <cuda_runtime.h>

// Gated DeltaNet single step, folded to ONE matvec:
//   qk = q . k ;  w = q - qk*beta*k ;  out = g*(w . S[:,v]) + qk*beta*v
// One warp per (b,h), 8 warps/CTA, float4 lanes.
// Triple-buffered pipeline (prefetch distance 2): ~16 LDG.128 in flight
// per thread continuously. __launch_bounds__(256,2): 128-reg budget.

#define DK 128
#define DV 128
#define WARPS_PER_CTA 8
#define BATCH 8
#define NBATCH (DK / BATCH)   // 16

__global__ __launch_bounds__(WARPS_PER_CTA * 32, 2)
void deltanet_step_kernel(const float* __restrict__ q,
                          const float* __restrict__ k,
                          const float* __restrict__ v,
                          const float* __restrict__ beta,
                          const float* __restrict__ gate,
                          const float* __restrict__ state,
                          float* __restrict__ out,
                          int BH) {
    const int warp = threadIdx.x >> 5;
    const int lane = threadIdx.x & 31;
    const int bh   = blockIdx.x * WARPS_PER_CTA + warp;
    if (bh >= BH) return;

    __shared__ float sw[WARPS_PER_CTA][DK];

    {
        const float4 q4 = reinterpret_cast<const float4*>(q + (size_t)bh * DK)[lane];
        const float4 k4 = reinterpret_cast<const float4*>(k + (size_t)bh * DK)[lane];

        float qk = q4.x * k4.x + q4.y * k4.y + q4.z * k4.z + q4.w * k4.w;
        #pragma unroll
        for (int off = 16; off > 0; off >>= 1)
            qk += __shfl_xor_sync(0xFFFFFFFFu, qk, off);

        const float qkb = qk * beta[bh];

        float4 w4;
        w4.x = fmaf(-qkb, k4.x, q4.x);
        w4.y = fmaf(-qkb, k4.y, q4.y);
        w4.z = fmaf(-qkb, k4.z, q4.z);
        w4.w = fmaf(-qkb, k4.w, q4.w);
        reinterpret_cast<float4*>(sw[warp])[lane] = w4;
        // stash qkb in lane-uniform shuffle-safe register via smem? cheaper:
        // recompute later — store in sw is full; keep in register below.
        __syncwarp();
        // keep qkb live through loop in a register (small cost)
        // (handled by moving epilogue constants below)
        // fallthrough
        // NOTE: qkb needed in epilogue; keep via variable outside this scope.
        // We re-declare below by recomputation-free hoist:
        // (see qkb_keep)
        __syncwarp();
        // export to outer scope
        *((float*)&w4) = qkb;  // reuse w4.x slot as carrier
        // store carrier to a per-thread register via volatile? Simpler: fall
        // through with goto-free structure below.
        // -- replaced by explicit outer variable; see below --
    }

    // Recompute scalars cheaply (L1-hot, negligible): avoids holding them
    // across the register-heavy loop.
    const float4* S = reinterpret_cast<const float4*>(state + (size_t)bh * (DK * DV));

    float4 acc = make_float4(0.f, 0.f, 0.f, 0.f);

    float4 bufA[BATCH];
    float4 bufB[BATCH];
    float4 bufC[BATCH];

    // Prologue: batches 0 and 1 in flight.
    #pragma unroll
    for (int i = 0; i < BATCH; ++i)
        bufA[i] = S[i * (DV / 4) + lane];
    #pragma unroll
    for (int i = 0; i < BATCH; ++i)
        bufB[i] = S[(BATCH + i) * (DV / 4) + lane];

    #pragma unroll
    for (int b = 0; b < NBATCH; ++b) {
        float4* cur = (b % 3 == 0) ? bufA : (b % 3 == 1) ? bufB : bufC;
        float4* pre = (b % 3 == 0) ? bufC : (b % 3 == 1) ? bufA : bufB;

        // Issue batch b+2 while batch b computes (b+1 is landing).
        if (b + 2 < NBATCH) {
            const int base = (b + 2) * BATCH;
            #pragma unroll
            for (int i = 0; i < BATCH; ++i)
                pre[i] = S[(base + i) * (DV / 4) + lane];
        }

        const int base = b * BATCH;
        #pragma unroll
        for (int i = 0; i < BATCH; ++i) {
            const float wc = sw[warp][base + i];
            acc.x = fmaf(wc, cur[i].x, acc.x);
            acc.y = fmaf(wc, cur[i].y, acc.y);
            acc.z = fmaf(wc, cur[i].z, acc.z);
            acc.w = fmaf(wc, cur[i].w, acc.w);
        }
    }

    // Epilogue scalars (cheap re-reads, these lines are L1/L2 hot).
    {
        const float4 q4 = reinterpret_cast<const float4*>(q + (size_t)bh * DK)[lane];
        const float4 k4 = reinterpret_cast<const float4*>(k + (size_t)bh * DK)[lane];
        float qk = q4.x * k4.x + q4.y * k4.y + q4.z * k4.z + q4.w * k4.w;
        #pragma unroll
        for (int off = 16; off > 0; off >>= 1)
            qk += __shfl_xor_sync(0xFFFFFFFFu, qk, off);
        const float qkb = qk * beta[bh];
        const float g   = gate[bh];

        const float4 vv = reinterpret_cast<const float4*>(v + (size_t)bh * DV)[lane];

        float4 o;
        o.x = fmaf(g, acc.x, qkb * vv.x);
        o.y = fmaf(g, acc.y, qkb * vv.y);
        o.z = fmaf(g, acc.z, qkb * vv.z);
        o.w = fmaf(g, acc.w, qkb * vv.w);
        reinterpret_cast<float4*>(out + (size_t)bh * DV)[lane] = o;
    }
}

extern "C" void kernel_launch(void* const* d_in, const int* in_sizes, int n_in,
                              void* d_out, int out_size) {
    const float* q     = (const float*)d_in[0];
    const float* k     = (const float*)d_in[1];
    const float* v     = (const float*)d_in[2];
    const float* beta  = (const float*)d_in[3];
    const float* gate  = (const float*)d_in[4];
    const float* state = (const float*)d_in[5];
    float* out = (float*)d_out;

    const int BH = in_sizes[3];   // beta: B*H elements
    const int grid = (BH + WARPS_PER_CTA - 1) / WARPS_PER_CTA;

    deltanet_step_kernel<<<grid, WARPS_PER_CTA * 32>>>(q, k, v, beta, gate, state, out, BH);
}